// round 6
// baseline (speedup 1.0000x reference)
#include <cuda_runtime.h>
#include <math.h>

#define BN 8
#define SN 128
#define TN 512
#define DT 256
#define DF 80
#define NEGV (-1e9f)

typedef unsigned long long ull;

__device__ float g_ht[BN * SN * DT];
__device__ float g_mt[BN * TN * DT];
__device__ float g_lpT[BN * TN * SN];   // transposed log_a_soft [b][t][s]
__device__ float W1t[768 * DT];
__device__ float W2t[DT * DT];
__device__ float F1t[240 * DT];
__device__ float F2t[768 * DT];
__device__ float F3t[DT * DT];

__device__ __forceinline__ ull pk2(float lo, float hi) {
    ull r; asm("mov.b64 %0,{%1,%2};" : "=l"(r) : "f"(lo), "f"(hi)); return r;
}
__device__ __forceinline__ void upk2(ull v, float& lo, float& hi) {
    asm("mov.b64 {%0,%1},%2;" : "=f"(lo), "=f"(hi) : "l"(v));
}
__device__ __forceinline__ ull fma2(ull a, ull b, ull c) {
    ull d; asm("fma.rn.f32x2 %0,%1,%2,%3;" : "=l"(d) : "l"(a), "l"(b), "l"(c)); return d;
}
__device__ __forceinline__ ull add2(ull a, ull b) {
    ull d; asm("add.rn.f32x2 %0,%1,%2;" : "=l"(d) : "l"(a), "l"(b)); return d;
}
__device__ __forceinline__ ull ld64s(const float* p) { return *reinterpret_cast<const ull*>(p); }

// --------------------------------------------------------------------------
// Coalesced weight transposes.
// --------------------------------------------------------------------------
__global__ __launch_bounds__(256) void transpose_kernel(const float* __restrict__ W1,
                                                        const float* __restrict__ W2,
                                                        const float* __restrict__ F1,
                                                        const float* __restrict__ F2,
                                                        const float* __restrict__ F3) {
    __shared__ float tile[32][33];
    int blk = blockIdx.x;
    const float* src; float* dst; int C; int t;
    if (blk < 192)      { src = W1; dst = W1t; C = 768; t = blk; }
    else if (blk < 256) { src = W2; dst = W2t; C = 256; t = blk - 192; }
    else if (blk < 320) { src = F1; dst = F1t; C = 240; t = blk - 256; }
    else if (blk < 512) { src = F2; dst = F2t; C = 768; t = blk - 320; }
    else                { src = F3; dst = F3t; C = 256; t = blk - 512; }
    int Ct = (C + 31) >> 5;
    int tr = t / Ct, tc = t - tr * Ct;
    int tx = threadIdx.x & 31, ty = threadIdx.x >> 5;
#pragma unroll
    for (int i = 0; i < 4; ++i) {
        int r = tr * 32 + ty + i * 8, cc = tc * 32 + tx;
        tile[ty + i * 8][tx] = (cc < C) ? src[(size_t)r * C + cc] : 0.f;
    }
    __syncthreads();
#pragma unroll
    for (int i = 0; i < 4; ++i) {
        int cc = tc * 32 + ty + i * 8, r = tr * 32 + tx;
        if (cc < C) dst[(size_t)cc * 256 + r] = tile[tx][ty + i * 8];
    }
}

// --------------------------------------------------------------------------
// Packed conv helpers (identical math to R3).
// --------------------------------------------------------------------------
template <int NC, int RS, int NP>
__device__ __forceinline__ void conv3pairs(const float* src, const float* wt, float bias, ull* acc) {
    ull bb = pk2(bias, bias);
#pragma unroll
    for (int i = 0; i < NP; ++i) acc[i] = bb;
    for (int ci = 0; ci < NC; ++ci) {
        const float* x = src + ci * RS;
        ull P[NP + 1];
#pragma unroll
        for (int i = 0; i <= NP; ++i) P[i] = ld64s(x + 2 * i);
        float lo[NP + 1], hi[NP + 1];
#pragma unroll
        for (int i = 0; i <= NP; ++i) upk2(P[i], lo[i], hi[i]);
        ull O[NP];
#pragma unroll
        for (int i = 0; i < NP; ++i) O[i] = pk2(hi[i], lo[i + 1]);
        const float* wp = wt + ci * 3 * DT;
        ull w0 = pk2(wp[0], wp[0]), w1 = pk2(wp[DT], wp[DT]), w2 = pk2(wp[2 * DT], wp[2 * DT]);
#pragma unroll
        for (int i = 0; i < NP; ++i) acc[i] = fma2(w0, P[i], acc[i]);
#pragma unroll
        for (int i = 0; i < NP; ++i) acc[i] = fma2(w1, O[i], acc[i]);
#pragma unroll
        for (int i = 0; i < NP; ++i) acc[i] = fma2(w2, P[i + 1], acc[i]);
    }
}

template <int NP>
__device__ __forceinline__ void conv1pairs(const float* src, int RS, const float* wt, float bias, ull* acc) {
    ull bb = pk2(bias, bias);
#pragma unroll
    for (int i = 0; i < NP; ++i) acc[i] = bb;
    for (int ci = 0; ci < DT; ++ci) {
        const float* x = src + ci * RS;
        float w = wt[ci * DT];
        ull wpk = pk2(w, w);
#pragma unroll
        for (int i = 0; i < NP; ++i) acc[i] = fma2(wpk, ld64s(x + 2 * i), acc[i]);
    }
}

// --------------------------------------------------------------------------
// Fused conv: blocks [0,256) feat path, [256,320) text path.  256 thr = chan.
// --------------------------------------------------------------------------
__global__ __launch_bounds__(256) void conv_all_kernel(const float* __restrict__ h,
                                                       const float* __restrict__ m,
                                                       const float* __restrict__ b1v,
                                                       const float* __restrict__ b2v,
                                                       const float* __restrict__ g1v,
                                                       const float* __restrict__ g2v,
                                                       const float* __restrict__ g3v) {
    __shared__ __align__(16) float sbuf[10304];
    int tid = threadIdx.x, blk = blockIdx.x, c = tid;
    if (blk < 256) {
        float* mT = sbuf;            // [80][20]
        float* A0 = sbuf + 1600;     // [256][18]
        float* B0 = sbuf + 6208;     // [256][16]
        int b = blk >> 5, t0 = (blk & 31) << 4;
        for (int idx = tid; idx < 1600; idx += 256) {
            int p = idx / 80, ci = idx - p * 80;
            int t = t0 - 2 + p;
            mT[ci * 20 + p] = (t >= 0 && t < TN) ? m[((size_t)(b * TN + t)) * DF + ci] : 0.f;
        }
        __syncthreads();
        {
            ull acc[9];
            conv3pairs<DF, 20, 9>(mT, F1t + c, g1v[c], acc);
#pragma unroll
            for (int i = 0; i < 9; ++i) {
                float v0, v1; upk2(acc[i], v0, v1);
                int g = t0 - 1 + 2 * i;
                A0[c * 18 + 2 * i] = (g >= 0 && g < TN) ? fmaxf(v0, 0.f) : 0.f;
                ++g;
                A0[c * 18 + 2 * i + 1] = (g >= 0 && g < TN) ? fmaxf(v1, 0.f) : 0.f;
            }
        }
        __syncthreads();
        {
            ull acc[8];
            conv3pairs<DT, 18, 8>(A0, F2t + c, g2v[c], acc);
#pragma unroll
            for (int i = 0; i < 8; ++i) {
                float v0, v1; upk2(acc[i], v0, v1);
                B0[c * 16 + 2 * i] = fmaxf(v0, 0.f);
                B0[c * 16 + 2 * i + 1] = fmaxf(v1, 0.f);
            }
        }
        __syncthreads();
        {
            ull acc[8];
            conv1pairs<8>(B0, 16, F3t + c, g3v[c], acc);
#pragma unroll
            for (int i = 0; i < 8; ++i) {
                float v0, v1; upk2(acc[i], v0, v1);
                g_mt[((size_t)(b * TN + t0 + 2 * i)) * DT + c] = v0;
                g_mt[((size_t)(b * TN + t0 + 2 * i + 1)) * DT + c] = v1;
            }
        }
    } else {
        float* hT = sbuf;            // [256][18]
        float* yT = sbuf + 4608;     // [256][16]
        int q = blk - 256;
        int b = q >> 3, s0 = (q & 7) << 4;
        for (int idx = tid; idx < 4608; idx += 256) {
            int p = idx >> 8, cc = idx & 255;
            int s = s0 - 1 + p;
            hT[cc * 18 + p] = (s >= 0 && s < SN) ? h[((size_t)(b * SN + s)) * DT + cc] : 0.f;
        }
        __syncthreads();
        {
            ull acc[8];
            conv3pairs<DT, 18, 8>(hT, W1t + c, b1v[c], acc);
#pragma unroll
            for (int i = 0; i < 8; ++i) {
                float v0, v1; upk2(acc[i], v0, v1);
                yT[c * 16 + 2 * i] = fmaxf(v0, 0.f);
                yT[c * 16 + 2 * i + 1] = fmaxf(v1, 0.f);
            }
        }
        __syncthreads();
        {
            ull acc[8];
            conv1pairs<8>(yT, 16, W2t + c, b2v[c], acc);
#pragma unroll
            for (int i = 0; i < 8; ++i) {
                float v0, v1; upk2(acc[i], v0, v1);
                g_ht[((size_t)(b * SN + s0 + 2 * i)) * DT + c] = v0;
                g_ht[((size_t)(b * SN + s0 + 2 * i + 1)) * DT + c] = v1;
            }
        }
    }
}

// --------------------------------------------------------------------------
// L2 distance + log_softmax + transposed side-output g_lpT (same as R5).
// --------------------------------------------------------------------------
__global__ __launch_bounds__(128) void dist_softmax_kernel(const int* __restrict__ tokl,
                                                           float* __restrict__ out) {
    __shared__ float A[SN][33];
    __shared__ __align__(8) float Bs[32][18];
    __shared__ float Z[SN][17];
    __shared__ float mls[16];
    int b = blockIdx.x, t0 = blockIdx.y * 16;
    int tid = threadIdx.x;
    int ts = tid >> 2, tt = tid & 3;
    ull acc[4][2];
#pragma unroll
    for (int r = 0; r < 4; ++r) { acc[r][0] = 0ULL; acc[r][1] = 0ULL; }
    for (int cch = 0; cch < 8; ++cch) {
        int k0 = cch * 32;
        for (int idx = tid; idx < SN * 32; idx += 128) {
            int s = idx >> 5, kk = idx & 31;
            A[s][kk] = g_ht[((size_t)(b * SN + s)) * DT + k0 + kk];
        }
        for (int idx = tid; idx < 16 * 32; idx += 128) {
            int t = idx >> 5, kk = idx & 31;
            Bs[kk][t] = -g_mt[((size_t)(b * TN + t0 + t)) * DT + k0 + kk];
        }
        __syncthreads();
#pragma unroll 4
        for (int kk = 0; kk < 32; ++kk) {
            ull bq0 = ld64s(&Bs[kk][tt * 4]);
            ull bq1 = ld64s(&Bs[kk][tt * 4 + 2]);
#pragma unroll
            for (int r = 0; r < 4; ++r) {
                float av = A[ts * 4 + r][kk];
                ull ap = pk2(av, av);
                ull d0 = add2(ap, bq0);
                acc[r][0] = fma2(d0, d0, acc[r][0]);
                ull d1 = add2(ap, bq1);
                acc[r][1] = fma2(d1, d1, acc[r][1]);
            }
        }
        __syncthreads();
    }
    int tok = tokl[b];
#pragma unroll
    for (int r = 0; r < 4; ++r) {
        int s = ts * 4 + r;
        float v[4];
        upk2(acc[r][0], v[0], v[1]);
        upk2(acc[r][1], v[2], v[3]);
#pragma unroll
        for (int j = 0; j < 4; ++j) {
            float dd = (s < tok) ? sqrtf(fmaxf(v[j], 0.f)) : 0.f;
            Z[s][tt * 4 + j] = -dd;
        }
    }
    __syncthreads();
    int tcol = tid >> 3, l = tid & 7;
    float mx = -3.4e38f;
#pragma unroll
    for (int i2 = 0; i2 < 16; ++i2) mx = fmaxf(mx, Z[l * 16 + i2][tcol]);
    mx = fmaxf(mx, __shfl_xor_sync(0xffffffffu, mx, 4));
    mx = fmaxf(mx, __shfl_xor_sync(0xffffffffu, mx, 2));
    mx = fmaxf(mx, __shfl_xor_sync(0xffffffffu, mx, 1));
    float sm = 0.f;
#pragma unroll
    for (int i2 = 0; i2 < 16; ++i2) sm += expf(Z[l * 16 + i2][tcol] - mx);
    sm += __shfl_xor_sync(0xffffffffu, sm, 4);
    sm += __shfl_xor_sync(0xffffffffu, sm, 2);
    sm += __shfl_xor_sync(0xffffffffu, sm, 1);
    if (l == 0) mls[tcol] = mx + logf(sm);
    __syncthreads();
    float* out_log = out + BN * SN;
    float* out_hard = out + BN * SN + (size_t)BN * SN * TN;
    for (int idx = tid; idx < SN * 16; idx += 128) {
        int s = idx >> 4, tl = idx & 15;
        size_t o = ((size_t)(b * SN + s)) * TN + t0 + tl;
        out_log[o] = Z[s][tl] - mls[tl];
        out_hard[o] = 0.f;
    }
    for (int idx = tid; idx < 16 * SN; idx += 128) {
        int tl = idx >> 7, s = idx & 127;
        g_lpT[((size_t)(b * TN) + t0 + tl) * SN + s] = Z[s][tl] - mls[tl];
    }
}

// --------------------------------------------------------------------------
// MAS v3: warp-0 DP with register double-buffered loads (no smem staging,
// no block barriers in the loop); ballot-packed choice bits (8 KB);
// prefetch-select backtrack.
// --------------------------------------------------------------------------
__device__ __forceinline__ void dp_step(float4 Lq, int j, int ln,
                                        float& q0, float& q1, float& q2, float& q3,
                                        float& up, unsigned* chw) {
    if (j == 0) {
        q0 = (ln == 0) ? Lq.x : NEGV;
        q1 = NEGV; q2 = NEGV; q3 = NEGV;
        if (ln < 4) chw[ln] = 0u;
        up = __shfl_up_sync(0xffffffffu, q3, 1);
    } else {
        float s0 = (ln == 0) ? NEGV : up;
        unsigned p0 = (unsigned)(s0 >= q0);
        unsigned p1 = (unsigned)(q0 >= q1);
        unsigned p2 = (unsigned)(q1 >= q2);
        unsigned p3 = (unsigned)(q2 >= q3);
        float n3 = Lq.w + fmaxf(q3, q2);
        float nup = __shfl_up_sync(0xffffffffu, n3, 1);
        float n0 = Lq.x + fmaxf(q0, s0);
        float n1 = Lq.y + fmaxf(q1, q0);
        float n2 = Lq.z + fmaxf(q2, q1);
        unsigned w0 = __ballot_sync(0xffffffffu, p0 != 0u);
        unsigned w1 = __ballot_sync(0xffffffffu, p1 != 0u);
        unsigned w2 = __ballot_sync(0xffffffffu, p2 != 0u);
        unsigned w3 = __ballot_sync(0xffffffffu, p3 != 0u);
        q0 = n0; q1 = n1; q2 = n2; q3 = n3; up = nup;
        if (ln < 4) {
            unsigned ws = (ln == 0) ? w0 : (ln == 1) ? w1 : (ln == 2) ? w2 : w3;
            chw[j * 4 + ln] = ws;
        }
    }
}

__global__ __launch_bounds__(128) void mas_kernel(const int* __restrict__ tokl,
                                                  const int* __restrict__ featl,
                                                  float* __restrict__ out) {
    __shared__ unsigned chw[TN * 4];    // bit(i,j) = chw[j*4 + (i&3)] >> (i>>2)
    __shared__ int dsh[SN];
    int b = blockIdx.x;
    int tid = threadIdx.x;
    float* hard = out + BN * SN + (size_t)BN * SN * TN + ((size_t)b * SN) * TN;
    float* dout = out + (size_t)b * SN;
    dsh[tid] = 0;
    __syncthreads();
    if (tid < 32) {
        int ln = tid;
        const float4* src = reinterpret_cast<const float4*>(g_lpT + (size_t)b * TN * SN) + ln;
        float4 A[8], Bq[8];
#pragma unroll
        for (int q = 0; q < 8; ++q) A[q] = src[(size_t)q * 32];
        float q0 = NEGV, q1 = NEGV, q2 = NEGV, q3 = NEGV, up = NEGV;
#pragma unroll 1
        for (int c = 0; c < 64; c += 2) {
#pragma unroll
            for (int q = 0; q < 8; ++q) Bq[q] = src[(size_t)((c + 1) * 8 + q) * 32];
#pragma unroll
            for (int jj = 0; jj < 8; ++jj)
                dp_step(A[jj], c * 8 + jj, ln, q0, q1, q2, q3, up, chw);
            if (c + 2 < 64) {
#pragma unroll
                for (int q = 0; q < 8; ++q) A[q] = src[(size_t)((c + 2) * 8 + q) * 32];
            }
#pragma unroll
            for (int jj = 0; jj < 8; ++jj)
                dp_step(Bq[jj], c * 8 + 8 + jj, ln, q0, q1, q2, q3, up, chw);
        }
        __syncwarp();
        if (tid == 0) {
            int i = tokl[b] - 1;
            int fl = featl[b];
            int j = fl - 1;
            unsigned wcur = chw[j * 4 + (i & 3)];
            int bit = (j > 0) ? (int)((wcur >> (i >> 2)) & 1u) : 0;
            unsigned W0 = 0, W1 = 0;
            if (j >= 1) {
                int i1 = (i > 0) ? i - 1 : 0;
                W0 = chw[(j - 1) * 4 + (i & 3)];
                W1 = chw[(j - 1) * 4 + (i1 & 3)];
            }
            int run = 0, previ = i;
            while (j > 0) {
                hard[(size_t)i * TN + j] = 1.0f;
                ++run;
                int inext = i - bit;
                unsigned wsel = bit ? W1 : W0;
                int nbit = (int)((wsel >> (inext >> 2)) & 1u);
                if (j >= 2) {
                    int i1 = (inext > 0) ? inext - 1 : 0;
                    W0 = chw[(j - 2) * 4 + (inext & 3)];
                    W1 = chw[(j - 2) * 4 + (i1 & 3)];
                }
                if (inext != i) { dsh[previ] = run; run = 0; previ = inext; }
                i = inext; bit = nbit;
                --j;
            }
            hard[(size_t)i * TN] = 1.0f;
            ++run;
            dsh[previ] = run;
        }
    }
    __syncthreads();
    dout[tid] = (float)dsh[tid];
}

extern "C" void kernel_launch(void* const* d_in, const int* in_sizes, int n_in,
                              void* d_out, int out_size) {
    const float* h  = (const float*)d_in[0];
    const float* m  = (const float*)d_in[1];
    const int* tokl = (const int*)d_in[2];
    const int* fetl = (const int*)d_in[3];
    const float* W1 = (const float*)d_in[5];
    const float* b1 = (const float*)d_in[6];
    const float* W2 = (const float*)d_in[7];
    const float* b2 = (const float*)d_in[8];
    const float* F1 = (const float*)d_in[9];
    const float* g1 = (const float*)d_in[10];
    const float* F2 = (const float*)d_in[11];
    const float* g2 = (const float*)d_in[12];
    const float* F3 = (const float*)d_in[13];
    const float* g3 = (const float*)d_in[14];
    float* out = (float*)d_out;

    transpose_kernel<<<576, 256>>>(W1, W2, F1, F2, F3);
    conv_all_kernel<<<320, 256>>>(h, m, b1, b2, g1, g2, g3);
    dist_softmax_kernel<<<dim3(BN, TN / 16), 128>>>(tokl, out);
    mas_kernel<<<BN, 128>>>(tokl, fetl, out);
}

// round 7
// speedup vs baseline: 1.2512x; 1.2512x over previous
#include <cuda_runtime.h>
#include <math.h>

#define BN 8
#define SN 128
#define TN 512
#define DT 256
#define DF 80
#define NEGV (-1e9f)

typedef unsigned long long ull;

__device__ float g_ht[BN * SN * DT];
__device__ float g_mt[BN * TN * DT];
__device__ float g_lpT[BN * TN * SN];   // transposed log_a_soft [b][t][s]
__device__ float W1t[768 * DT];
__device__ float W2t[DT * DT];
__device__ float F1t[240 * DT];
__device__ float F2t[768 * DT];
__device__ float F3t[DT * DT];

__device__ __forceinline__ ull pk2(float lo, float hi) {
    ull r; asm("mov.b64 %0,{%1,%2};" : "=l"(r) : "f"(lo), "f"(hi)); return r;
}
__device__ __forceinline__ void upk2(ull v, float& lo, float& hi) {
    asm("mov.b64 {%0,%1},%2;" : "=f"(lo), "=f"(hi) : "l"(v));
}
__device__ __forceinline__ ull fma2(ull a, ull b, ull c) {
    ull d; asm("fma.rn.f32x2 %0,%1,%2,%3;" : "=l"(d) : "l"(a), "l"(b), "l"(c)); return d;
}
__device__ __forceinline__ ull add2(ull a, ull b) {
    ull d; asm("add.rn.f32x2 %0,%1,%2;" : "=l"(d) : "l"(a), "l"(b)); return d;
}
__device__ __forceinline__ ull ld64s(const float* p) { return *reinterpret_cast<const ull*>(p); }

// --------------------------------------------------------------------------
// Coalesced weight transposes.
// --------------------------------------------------------------------------
__global__ __launch_bounds__(256) void transpose_kernel(const float* __restrict__ W1,
                                                        const float* __restrict__ W2,
                                                        const float* __restrict__ F1,
                                                        const float* __restrict__ F2,
                                                        const float* __restrict__ F3) {
    __shared__ float tile[32][33];
    int blk = blockIdx.x;
    const float* src; float* dst; int C; int t;
    if (blk < 192)      { src = W1; dst = W1t; C = 768; t = blk; }
    else if (blk < 256) { src = W2; dst = W2t; C = 256; t = blk - 192; }
    else if (blk < 320) { src = F1; dst = F1t; C = 240; t = blk - 256; }
    else if (blk < 512) { src = F2; dst = F2t; C = 768; t = blk - 320; }
    else                { src = F3; dst = F3t; C = 256; t = blk - 512; }
    int Ct = (C + 31) >> 5;
    int tr = t / Ct, tc = t - tr * Ct;
    int tx = threadIdx.x & 31, ty = threadIdx.x >> 5;
#pragma unroll
    for (int i = 0; i < 4; ++i) {
        int r = tr * 32 + ty + i * 8, cc = tc * 32 + tx;
        tile[ty + i * 8][tx] = (cc < C) ? src[(size_t)r * C + cc] : 0.f;
    }
    __syncthreads();
#pragma unroll
    for (int i = 0; i < 4; ++i) {
        int cc = tc * 32 + ty + i * 8, r = tr * 32 + tx;
        if (cc < C) dst[(size_t)cc * 256 + r] = tile[tx][ty + i * 8];
    }
}

// --------------------------------------------------------------------------
// Packed conv helpers.
// --------------------------------------------------------------------------
template <int NC, int RS, int NP>
__device__ __forceinline__ void conv3pairs(const float* src, const float* wt, float bias, ull* acc) {
    ull bb = pk2(bias, bias);
#pragma unroll
    for (int i = 0; i < NP; ++i) acc[i] = bb;
    for (int ci = 0; ci < NC; ++ci) {
        const float* x = src + ci * RS;
        ull P[NP + 1];
#pragma unroll
        for (int i = 0; i <= NP; ++i) P[i] = ld64s(x + 2 * i);
        float lo[NP + 1], hi[NP + 1];
#pragma unroll
        for (int i = 0; i <= NP; ++i) upk2(P[i], lo[i], hi[i]);
        ull O[NP];
#pragma unroll
        for (int i = 0; i < NP; ++i) O[i] = pk2(hi[i], lo[i + 1]);
        const float* wp = wt + ci * 3 * DT;
        ull w0 = pk2(wp[0], wp[0]), w1 = pk2(wp[DT], wp[DT]), w2 = pk2(wp[2 * DT], wp[2 * DT]);
#pragma unroll
        for (int i = 0; i < NP; ++i) acc[i] = fma2(w0, P[i], acc[i]);
#pragma unroll
        for (int i = 0; i < NP; ++i) acc[i] = fma2(w1, O[i], acc[i]);
#pragma unroll
        for (int i = 0; i < NP; ++i) acc[i] = fma2(w2, P[i + 1], acc[i]);
    }
}

template <int NP>
__device__ __forceinline__ void conv1pairs(const float* src, int RS, const float* wt, float bias, ull* acc) {
    ull bb = pk2(bias, bias);
#pragma unroll
    for (int i = 0; i < NP; ++i) acc[i] = bb;
    for (int ci = 0; ci < DT; ++ci) {
        const float* x = src + ci * RS;
        float w = wt[ci * DT];
        ull wpk = pk2(w, w);
#pragma unroll
        for (int i = 0; i < NP; ++i) acc[i] = fma2(wpk, ld64s(x + 2 * i), acc[i]);
    }
}

// --------------------------------------------------------------------------
// Fused conv: blocks [0,256) feat path, [256,320) text path.  256 thr = chan.
// --------------------------------------------------------------------------
__global__ __launch_bounds__(256) void conv_all_kernel(const float* __restrict__ h,
                                                       const float* __restrict__ m,
                                                       const float* __restrict__ b1v,
                                                       const float* __restrict__ b2v,
                                                       const float* __restrict__ g1v,
                                                       const float* __restrict__ g2v,
                                                       const float* __restrict__ g3v) {
    __shared__ __align__(16) float sbuf[10304];
    int tid = threadIdx.x, blk = blockIdx.x, c = tid;
    if (blk < 256) {
        float* mT = sbuf;            // [80][20]
        float* A0 = sbuf + 1600;     // [256][18]
        float* B0 = sbuf + 6208;     // [256][16]
        int b = blk >> 5, t0 = (blk & 31) << 4;
        for (int idx = tid; idx < 1600; idx += 256) {
            int p = idx / 80, ci = idx - p * 80;
            int t = t0 - 2 + p;
            mT[ci * 20 + p] = (t >= 0 && t < TN) ? m[((size_t)(b * TN + t)) * DF + ci] : 0.f;
        }
        __syncthreads();
        {
            ull acc[9];
            conv3pairs<DF, 20, 9>(mT, F1t + c, g1v[c], acc);
#pragma unroll
            for (int i = 0; i < 9; ++i) {
                float v0, v1; upk2(acc[i], v0, v1);
                int g = t0 - 1 + 2 * i;
                A0[c * 18 + 2 * i] = (g >= 0 && g < TN) ? fmaxf(v0, 0.f) : 0.f;
                ++g;
                A0[c * 18 + 2 * i + 1] = (g >= 0 && g < TN) ? fmaxf(v1, 0.f) : 0.f;
            }
        }
        __syncthreads();
        {
            ull acc[8];
            conv3pairs<DT, 18, 8>(A0, F2t + c, g2v[c], acc);
#pragma unroll
            for (int i = 0; i < 8; ++i) {
                float v0, v1; upk2(acc[i], v0, v1);
                B0[c * 16 + 2 * i] = fmaxf(v0, 0.f);
                B0[c * 16 + 2 * i + 1] = fmaxf(v1, 0.f);
            }
        }
        __syncthreads();
        {
            ull acc[8];
            conv1pairs<8>(B0, 16, F3t + c, g3v[c], acc);
#pragma unroll
            for (int i = 0; i < 8; ++i) {
                float v0, v1; upk2(acc[i], v0, v1);
                g_mt[((size_t)(b * TN + t0 + 2 * i)) * DT + c] = v0;
                g_mt[((size_t)(b * TN + t0 + 2 * i + 1)) * DT + c] = v1;
            }
        }
    } else {
        float* hT = sbuf;            // [256][18]
        float* yT = sbuf + 4608;     // [256][16]
        int q = blk - 256;
        int b = q >> 3, s0 = (q & 7) << 4;
        for (int idx = tid; idx < 4608; idx += 256) {
            int p = idx >> 8, cc = idx & 255;
            int s = s0 - 1 + p;
            hT[cc * 18 + p] = (s >= 0 && s < SN) ? h[((size_t)(b * SN + s)) * DT + cc] : 0.f;
        }
        __syncthreads();
        {
            ull acc[8];
            conv3pairs<DT, 18, 8>(hT, W1t + c, b1v[c], acc);
#pragma unroll
            for (int i = 0; i < 8; ++i) {
                float v0, v1; upk2(acc[i], v0, v1);
                yT[c * 16 + 2 * i] = fmaxf(v0, 0.f);
                yT[c * 16 + 2 * i + 1] = fmaxf(v1, 0.f);
            }
        }
        __syncthreads();
        {
            ull acc[8];
            conv1pairs<8>(yT, 16, W2t + c, b2v[c], acc);
#pragma unroll
            for (int i = 0; i < 8; ++i) {
                float v0, v1; upk2(acc[i], v0, v1);
                g_ht[((size_t)(b * SN + s0 + 2 * i)) * DT + c] = v0;
                g_ht[((size_t)(b * SN + s0 + 2 * i + 1)) * DT + c] = v1;
            }
        }
    }
}

// --------------------------------------------------------------------------
// L2 distance + log_softmax + transposed side-output g_lpT.
// --------------------------------------------------------------------------
__global__ __launch_bounds__(128) void dist_softmax_kernel(const int* __restrict__ tokl,
                                                           float* __restrict__ out) {
    __shared__ float A[SN][33];
    __shared__ __align__(8) float Bs[32][18];
    __shared__ float Z[SN][17];
    __shared__ float mls[16];
    int b = blockIdx.x, t0 = blockIdx.y * 16;
    int tid = threadIdx.x;
    int ts = tid >> 2, tt = tid & 3;
    ull acc[4][2];
#pragma unroll
    for (int r = 0; r < 4; ++r) { acc[r][0] = 0ULL; acc[r][1] = 0ULL; }
    for (int cch = 0; cch < 8; ++cch) {
        int k0 = cch * 32;
        for (int idx = tid; idx < SN * 32; idx += 128) {
            int s = idx >> 5, kk = idx & 31;
            A[s][kk] = g_ht[((size_t)(b * SN + s)) * DT + k0 + kk];
        }
        for (int idx = tid; idx < 16 * 32; idx += 128) {
            int t = idx >> 5, kk = idx & 31;
            Bs[kk][t] = -g_mt[((size_t)(b * TN + t0 + t)) * DT + k0 + kk];
        }
        __syncthreads();
#pragma unroll 4
        for (int kk = 0; kk < 32; ++kk) {
            ull bq0 = ld64s(&Bs[kk][tt * 4]);
            ull bq1 = ld64s(&Bs[kk][tt * 4 + 2]);
#pragma unroll
            for (int r = 0; r < 4; ++r) {
                float av = A[ts * 4 + r][kk];
                ull ap = pk2(av, av);
                ull d0 = add2(ap, bq0);
                acc[r][0] = fma2(d0, d0, acc[r][0]);
                ull d1 = add2(ap, bq1);
                acc[r][1] = fma2(d1, d1, acc[r][1]);
            }
        }
        __syncthreads();
    }
    int tok = tokl[b];
#pragma unroll
    for (int r = 0; r < 4; ++r) {
        int s = ts * 4 + r;
        float v[4];
        upk2(acc[r][0], v[0], v[1]);
        upk2(acc[r][1], v[2], v[3]);
#pragma unroll
        for (int j = 0; j < 4; ++j) {
            float dd = (s < tok) ? sqrtf(fmaxf(v[j], 0.f)) : 0.f;
            Z[s][tt * 4 + j] = -dd;
        }
    }
    __syncthreads();
    int tcol = tid >> 3, l = tid & 7;
    float mx = -3.4e38f;
#pragma unroll
    for (int i2 = 0; i2 < 16; ++i2) mx = fmaxf(mx, Z[l * 16 + i2][tcol]);
    mx = fmaxf(mx, __shfl_xor_sync(0xffffffffu, mx, 4));
    mx = fmaxf(mx, __shfl_xor_sync(0xffffffffu, mx, 2));
    mx = fmaxf(mx, __shfl_xor_sync(0xffffffffu, mx, 1));
    float sm = 0.f;
#pragma unroll
    for (int i2 = 0; i2 < 16; ++i2) sm += expf(Z[l * 16 + i2][tcol] - mx);
    sm += __shfl_xor_sync(0xffffffffu, sm, 4);
    sm += __shfl_xor_sync(0xffffffffu, sm, 2);
    sm += __shfl_xor_sync(0xffffffffu, sm, 1);
    if (l == 0) mls[tcol] = mx + logf(sm);
    __syncthreads();
    float* out_log = out + BN * SN;
    float* out_hard = out + BN * SN + (size_t)BN * SN * TN;
    for (int idx = tid; idx < SN * 16; idx += 128) {
        int s = idx >> 4, tl = idx & 15;
        size_t o = ((size_t)(b * SN + s)) * TN + t0 + tl;
        out_log[o] = Z[s][tl] - mls[tl];
        out_hard[o] = 0.f;
    }
    for (int idx = tid; idx < 16 * SN; idx += 128) {
        int tl = idx >> 7, s = idx & 127;
        g_lpT[((size_t)(b * TN) + t0 + tl) * SN + s] = Z[s][tl] - mls[tl];
    }
}

// --------------------------------------------------------------------------
// MAS v4: warp-0-only DP, register double-buffered float4 loads (v3 skeleton),
// per-lane nibble choice bits via one STS.U8 (v2 encoding, NO ballots),
// exactly one shfl per step.  Backtrack = v2.
// --------------------------------------------------------------------------
__device__ __forceinline__ void dp_step4(float4 Lq, int j, int ln,
                                         float& q0, float& q1, float& q2, float& q3,
                                         float& up, unsigned char* chb) {
    if (j == 0) {
        q0 = (ln == 0) ? Lq.x : NEGV;
        q1 = NEGV; q2 = NEGV; q3 = NEGV;
        chb[ln] = 0;
        up = __shfl_up_sync(0xffffffffu, q3, 1);
    } else {
        float s0 = (ln == 0) ? NEGV : up;
        unsigned bits = (unsigned)(s0 >= q0)
                      | ((unsigned)(q0 >= q1) << 1)
                      | ((unsigned)(q1 >= q2) << 2)
                      | ((unsigned)(q2 >= q3) << 3);
        float n3 = Lq.w + fmaxf(q3, q2);
        float nup = __shfl_up_sync(0xffffffffu, n3, 1);
        float n0 = Lq.x + fmaxf(q0, s0);
        float n1 = Lq.y + fmaxf(q1, q0);
        float n2 = Lq.z + fmaxf(q2, q1);
        q0 = n0; q1 = n1; q2 = n2; q3 = n3; up = nup;
        chb[j * 32 + ln] = (unsigned char)bits;
    }
}

__global__ __launch_bounds__(128) void mas_kernel(const int* __restrict__ tokl,
                                                  const int* __restrict__ featl,
                                                  float* __restrict__ out) {
    __shared__ unsigned char ch[TN * 32];   // [j][ln] nibble of rows 4ln..4ln+3
    __shared__ int dsh[SN];
    int b = blockIdx.x;
    int tid = threadIdx.x;
    float* hard = out + BN * SN + (size_t)BN * SN * TN + ((size_t)b * SN) * TN;
    float* dout = out + (size_t)b * SN;
    dsh[tid] = 0;
    __syncthreads();
    if (tid < 32) {
        int ln = tid;
        const float4* src = reinterpret_cast<const float4*>(g_lpT + (size_t)b * TN * SN) + ln;
        float4 A[8], Bq[8];
#pragma unroll
        for (int q = 0; q < 8; ++q) A[q] = src[(size_t)q * 32];
        float q0 = NEGV, q1 = NEGV, q2 = NEGV, q3 = NEGV, up = NEGV;
#pragma unroll 1
        for (int c = 0; c < 64; c += 2) {
#pragma unroll
            for (int q = 0; q < 8; ++q) Bq[q] = src[(size_t)((c + 1) * 8 + q) * 32];
#pragma unroll
            for (int jj = 0; jj < 8; ++jj)
                dp_step4(A[jj], c * 8 + jj, ln, q0, q1, q2, q3, up, ch);
            if (c + 2 < 64) {
#pragma unroll
                for (int q = 0; q < 8; ++q) A[q] = src[(size_t)((c + 2) * 8 + q) * 32];
            }
#pragma unroll
            for (int jj = 0; jj < 8; ++jj)
                dp_step4(Bq[jj], c * 8 + 8 + jj, ln, q0, q1, q2, q3, up, ch);
        }
        __syncwarp();
        if (tid == 0) {
            int i = tokl[b] - 1;
            int fl = featl[b];
            for (int j = TN - 1; j >= 0; --j) {
                if (j < fl) {
                    hard[(size_t)i * TN + j] = 1.0f;
                    dsh[i] += 1;
                    int bit = (ch[j * 32 + (i >> 2)] >> (i & 3)) & 1;
                    if (j > 0) i -= bit;
                }
            }
        }
    }
    __syncthreads();
    dout[tid] = (float)dsh[tid];
}

extern "C" void kernel_launch(void* const* d_in, const int* in_sizes, int n_in,
                              void* d_out, int out_size) {
    const float* h  = (const float*)d_in[0];
    const float* m  = (const float*)d_in[1];
    const int* tokl = (const int*)d_in[2];
    const int* fetl = (const int*)d_in[3];
    const float* W1 = (const float*)d_in[5];
    const float* b1 = (const float*)d_in[6];
    const float* W2 = (const float*)d_in[7];
    const float* b2 = (const float*)d_in[8];
    const float* F1 = (const float*)d_in[9];
    const float* g1 = (const float*)d_in[10];
    const float* F2 = (const float*)d_in[11];
    const float* g2 = (const float*)d_in[12];
    const float* F3 = (const float*)d_in[13];
    const float* g3 = (const float*)d_in[14];
    float* out = (float*)d_out;

    transpose_kernel<<<576, 256>>>(W1, W2, F1, F2, F3);
    conv_all_kernel<<<320, 256>>>(h, m, b1, b2, g1, g2, g3);
    dist_softmax_kernel<<<dim3(BN, TN / 16), 128>>>(tokl, out);
    mas_kernel<<<BN, 128>>>(tokl, fetl, out);
}

// round 8
// speedup vs baseline: 1.3362x; 1.0679x over previous
#include <cuda_runtime.h>
#include <math.h>

#define BN 8
#define SN 128
#define TN 512
#define DT 256
#define DF 80
#define NEGV (-1e9f)

typedef unsigned long long ull;

__device__ float g_ht[BN * SN * DT];
__device__ float g_mt[BN * TN * DT];
__device__ float g_lpT[BN * TN * SN];   // transposed log_a_soft [b][t][s]
__device__ float W1t[768 * DT];
__device__ float W2t[DT * DT];
__device__ float F1t[240 * DT];
__device__ float F2t[768 * DT];
__device__ float F3t[DT * DT];

__device__ __forceinline__ ull pk2(float lo, float hi) {
    ull r; asm("mov.b64 %0,{%1,%2};" : "=l"(r) : "f"(lo), "f"(hi)); return r;
}
__device__ __forceinline__ void upk2(ull v, float& lo, float& hi) {
    asm("mov.b64 {%0,%1},%2;" : "=f"(lo), "=f"(hi) : "l"(v));
}
__device__ __forceinline__ ull fma2(ull a, ull b, ull c) {
    ull d; asm("fma.rn.f32x2 %0,%1,%2,%3;" : "=l"(d) : "l"(a), "l"(b), "l"(c)); return d;
}
__device__ __forceinline__ ull add2(ull a, ull b) {
    ull d; asm("add.rn.f32x2 %0,%1,%2;" : "=l"(d) : "l"(a), "l"(b)); return d;
}
__device__ __forceinline__ ull ld64s(const float* p) { return *reinterpret_cast<const ull*>(p); }

// --------------------------------------------------------------------------
// Coalesced weight transposes.
// --------------------------------------------------------------------------
__global__ __launch_bounds__(256) void transpose_kernel(const float* __restrict__ W1,
                                                        const float* __restrict__ W2,
                                                        const float* __restrict__ F1,
                                                        const float* __restrict__ F2,
                                                        const float* __restrict__ F3) {
    __shared__ float tile[32][33];
    int blk = blockIdx.x;
    const float* src; float* dst; int C; int t;
    if (blk < 192)      { src = W1; dst = W1t; C = 768; t = blk; }
    else if (blk < 256) { src = W2; dst = W2t; C = 256; t = blk - 192; }
    else if (blk < 320) { src = F1; dst = F1t; C = 240; t = blk - 256; }
    else if (blk < 512) { src = F2; dst = F2t; C = 768; t = blk - 320; }
    else                { src = F3; dst = F3t; C = 256; t = blk - 512; }
    int Ct = (C + 31) >> 5;
    int tr = t / Ct, tc = t - tr * Ct;
    int tx = threadIdx.x & 31, ty = threadIdx.x >> 5;
#pragma unroll
    for (int i = 0; i < 4; ++i) {
        int r = tr * 32 + ty + i * 8, cc = tc * 32 + tx;
        tile[ty + i * 8][tx] = (cc < C) ? src[(size_t)r * C + cc] : 0.f;
    }
    __syncthreads();
#pragma unroll
    for (int i = 0; i < 4; ++i) {
        int cc = tc * 32 + ty + i * 8, r = tr * 32 + tx;
        if (cc < C) dst[(size_t)cc * 256 + r] = tile[tx][ty + i * 8];
    }
}

// --------------------------------------------------------------------------
// Packed conv helpers.
// --------------------------------------------------------------------------
template <int NC, int RS, int NP>
__device__ __forceinline__ void conv3pairs(const float* src, const float* wt, float bias, ull* acc) {
    ull bb = pk2(bias, bias);
#pragma unroll
    for (int i = 0; i < NP; ++i) acc[i] = bb;
    for (int ci = 0; ci < NC; ++ci) {
        const float* x = src + ci * RS;
        ull P[NP + 1];
#pragma unroll
        for (int i = 0; i <= NP; ++i) P[i] = ld64s(x + 2 * i);
        float lo[NP + 1], hi[NP + 1];
#pragma unroll
        for (int i = 0; i <= NP; ++i) upk2(P[i], lo[i], hi[i]);
        ull O[NP];
#pragma unroll
        for (int i = 0; i < NP; ++i) O[i] = pk2(hi[i], lo[i + 1]);
        const float* wp = wt + ci * 3 * DT;
        ull w0 = pk2(wp[0], wp[0]), w1 = pk2(wp[DT], wp[DT]), w2 = pk2(wp[2 * DT], wp[2 * DT]);
#pragma unroll
        for (int i = 0; i < NP; ++i) acc[i] = fma2(w0, P[i], acc[i]);
#pragma unroll
        for (int i = 0; i < NP; ++i) acc[i] = fma2(w1, O[i], acc[i]);
#pragma unroll
        for (int i = 0; i < NP; ++i) acc[i] = fma2(w2, P[i + 1], acc[i]);
    }
}

// RS must be a multiple of 4 and rows 16B-aligned (true for B0/yT, RS=16).
template <int NP>
__device__ __forceinline__ void conv1pairs(const float* src, int RS, const float* wt, float bias, ull* acc) {
    ull bb = pk2(bias, bias);
#pragma unroll
    for (int i = 0; i < NP; ++i) acc[i] = bb;
    for (int ci = 0; ci < DT; ++ci) {
        const float4* x4 = reinterpret_cast<const float4*>(src + ci * RS);
        float w = wt[ci * DT];
        ull wpk = pk2(w, w);
#pragma unroll
        for (int i = 0; i < NP / 2; ++i) {
            float4 v = x4[i];
            acc[2 * i]     = fma2(wpk, pk2(v.x, v.y), acc[2 * i]);
            acc[2 * i + 1] = fma2(wpk, pk2(v.z, v.w), acc[2 * i + 1]);
        }
    }
}

// --------------------------------------------------------------------------
// Fused conv: blocks [0,256) feat path, [256,320) text path.  256 thr = chan.
// --------------------------------------------------------------------------
__global__ __launch_bounds__(256) void conv_all_kernel(const float* __restrict__ h,
                                                       const float* __restrict__ m,
                                                       const float* __restrict__ b1v,
                                                       const float* __restrict__ b2v,
                                                       const float* __restrict__ g1v,
                                                       const float* __restrict__ g2v,
                                                       const float* __restrict__ g3v) {
    __shared__ __align__(16) float sbuf[10304];
    int tid = threadIdx.x, blk = blockIdx.x, c = tid;
    if (blk < 256) {
        float* mT = sbuf;            // [80][20]
        float* A0 = sbuf + 1600;     // [256][18]
        float* B0 = sbuf + 6208;     // [256][16]
        int b = blk >> 5, t0 = (blk & 31) << 4;
        for (int idx = tid; idx < 1600; idx += 256) {
            int p = idx / 80, ci = idx - p * 80;
            int t = t0 - 2 + p;
            mT[ci * 20 + p] = (t >= 0 && t < TN) ? m[((size_t)(b * TN + t)) * DF + ci] : 0.f;
        }
        __syncthreads();
        {
            ull acc[9];
            conv3pairs<DF, 20, 9>(mT, F1t + c, g1v[c], acc);
#pragma unroll
            for (int i = 0; i < 9; ++i) {
                float v0, v1; upk2(acc[i], v0, v1);
                int g = t0 - 1 + 2 * i;
                A0[c * 18 + 2 * i] = (g >= 0 && g < TN) ? fmaxf(v0, 0.f) : 0.f;
                ++g;
                A0[c * 18 + 2 * i + 1] = (g >= 0 && g < TN) ? fmaxf(v1, 0.f) : 0.f;
            }
        }
        __syncthreads();
        {
            ull acc[8];
            conv3pairs<DT, 18, 8>(A0, F2t + c, g2v[c], acc);
#pragma unroll
            for (int i = 0; i < 8; ++i) {
                float v0, v1; upk2(acc[i], v0, v1);
                B0[c * 16 + 2 * i] = fmaxf(v0, 0.f);
                B0[c * 16 + 2 * i + 1] = fmaxf(v1, 0.f);
            }
        }
        __syncthreads();
        {
            ull acc[8];
            conv1pairs<8>(B0, 16, F3t + c, g3v[c], acc);
#pragma unroll
            for (int i = 0; i < 8; ++i) {
                float v0, v1; upk2(acc[i], v0, v1);
                g_mt[((size_t)(b * TN + t0 + 2 * i)) * DT + c] = v0;
                g_mt[((size_t)(b * TN + t0 + 2 * i + 1)) * DT + c] = v1;
            }
        }
    } else {
        float* hT = sbuf;            // [256][18]
        float* yT = sbuf + 4608;     // [256][16]
        int q = blk - 256;
        int b = q >> 3, s0 = (q & 7) << 4;
        for (int idx = tid; idx < 4608; idx += 256) {
            int p = idx >> 8, cc = idx & 255;
            int s = s0 - 1 + p;
            hT[cc * 18 + p] = (s >= 0 && s < SN) ? h[((size_t)(b * SN + s)) * DT + cc] : 0.f;
        }
        __syncthreads();
        {
            ull acc[8];
            conv3pairs<DT, 18, 8>(hT, W1t + c, b1v[c], acc);
#pragma unroll
            for (int i = 0; i < 8; ++i) {
                float v0, v1; upk2(acc[i], v0, v1);
                yT[c * 16 + 2 * i] = fmaxf(v0, 0.f);
                yT[c * 16 + 2 * i + 1] = fmaxf(v1, 0.f);
            }
        }
        __syncthreads();
        {
            ull acc[8];
            conv1pairs<8>(yT, 16, W2t + c, b2v[c], acc);
#pragma unroll
            for (int i = 0; i < 8; ++i) {
                float v0, v1; upk2(acc[i], v0, v1);
                g_ht[((size_t)(b * SN + s0 + 2 * i)) * DT + c] = v0;
                g_ht[((size_t)(b * SN + s0 + 2 * i + 1)) * DT + c] = v1;
            }
        }
    }
}

// --------------------------------------------------------------------------
// L2 distance + log_softmax + transposed side-output g_lpT.
// --------------------------------------------------------------------------
__global__ __launch_bounds__(128) void dist_softmax_kernel(const int* __restrict__ tokl,
                                                           float* __restrict__ out) {
    __shared__ float A[SN][33];
    __shared__ __align__(8) float Bs[32][18];
    __shared__ float Z[SN][17];
    __shared__ float mls[16];
    int b = blockIdx.x, t0 = blockIdx.y * 16;
    int tid = threadIdx.x;
    int ts = tid >> 2, tt = tid & 3;
    ull acc[4][2];
#pragma unroll
    for (int r = 0; r < 4; ++r) { acc[r][0] = 0ULL; acc[r][1] = 0ULL; }
    for (int cch = 0; cch < 8; ++cch) {
        int k0 = cch * 32;
        for (int idx = tid; idx < SN * 32; idx += 128) {
            int s = idx >> 5, kk = idx & 31;
            A[s][kk] = g_ht[((size_t)(b * SN + s)) * DT + k0 + kk];
        }
        for (int idx = tid; idx < 16 * 32; idx += 128) {
            int t = idx >> 5, kk = idx & 31;
            Bs[kk][t] = -g_mt[((size_t)(b * TN + t0 + t)) * DT + k0 + kk];
        }
        __syncthreads();
#pragma unroll 4
        for (int kk = 0; kk < 32; ++kk) {
            ull bq0 = ld64s(&Bs[kk][tt * 4]);
            ull bq1 = ld64s(&Bs[kk][tt * 4 + 2]);
#pragma unroll
            for (int r = 0; r < 4; ++r) {
                float av = A[ts * 4 + r][kk];
                ull ap = pk2(av, av);
                ull d0 = add2(ap, bq0);
                acc[r][0] = fma2(d0, d0, acc[r][0]);
                ull d1 = add2(ap, bq1);
                acc[r][1] = fma2(d1, d1, acc[r][1]);
            }
        }
        __syncthreads();
    }
    int tok = tokl[b];
#pragma unroll
    for (int r = 0; r < 4; ++r) {
        int s = ts * 4 + r;
        float v[4];
        upk2(acc[r][0], v[0], v[1]);
        upk2(acc[r][1], v[2], v[3]);
#pragma unroll
        for (int j = 0; j < 4; ++j) {
            float dd = (s < tok) ? sqrtf(fmaxf(v[j], 0.f)) : 0.f;
            Z[s][tt * 4 + j] = -dd;
        }
    }
    __syncthreads();
    int tcol = tid >> 3, l = tid & 7;
    float mx = -3.4e38f;
#pragma unroll
    for (int i2 = 0; i2 < 16; ++i2) mx = fmaxf(mx, Z[l * 16 + i2][tcol]);
    mx = fmaxf(mx, __shfl_xor_sync(0xffffffffu, mx, 4));
    mx = fmaxf(mx, __shfl_xor_sync(0xffffffffu, mx, 2));
    mx = fmaxf(mx, __shfl_xor_sync(0xffffffffu, mx, 1));
    float sm = 0.f;
#pragma unroll
    for (int i2 = 0; i2 < 16; ++i2) sm += expf(Z[l * 16 + i2][tcol] - mx);
    sm += __shfl_xor_sync(0xffffffffu, sm, 4);
    sm += __shfl_xor_sync(0xffffffffu, sm, 2);
    sm += __shfl_xor_sync(0xffffffffu, sm, 1);
    if (l == 0) mls[tcol] = mx + logf(sm);
    __syncthreads();
    float* out_log = out + BN * SN;
    float* out_hard = out + BN * SN + (size_t)BN * SN * TN;
    for (int idx = tid; idx < SN * 16; idx += 128) {
        int s = idx >> 4, tl = idx & 15;
        size_t o = ((size_t)(b * SN + s)) * TN + t0 + tl;
        out_log[o] = Z[s][tl] - mls[tl];
        out_hard[o] = 0.f;
    }
    for (int idx = tid; idx < 16 * SN; idx += 128) {
        int tl = idx >> 7, s = idx & 127;
        g_lpT[((size_t)(b * TN) + t0 + tl) * SN + s] = Z[s][tl] - mls[tl];
    }
}

// --------------------------------------------------------------------------
// MAS v5: branch-free steady DP loop (group 0 peeled), register double-buffer
// prefetch, nibble choice bits via STS.U8, dual-prefetch backtrack.
// --------------------------------------------------------------------------
__device__ __forceinline__ void dpn(float4 Lq, int j, int ln,
                                    float& q0, float& q1, float& q2, float& q3,
                                    float& up, unsigned char* chb) {
    float s0 = (ln == 0) ? NEGV : up;
    unsigned bits = (unsigned)(s0 >= q0)
                  | ((unsigned)(q0 >= q1) << 1)
                  | ((unsigned)(q1 >= q2) << 2)
                  | ((unsigned)(q2 >= q3) << 3);
    float n3 = Lq.w + fmaxf(q3, q2);
    float nup = __shfl_up_sync(0xffffffffu, n3, 1);
    float n0 = Lq.x + fmaxf(q0, s0);
    float n1 = Lq.y + fmaxf(q1, q0);
    float n2 = Lq.z + fmaxf(q2, q1);
    q0 = n0; q1 = n1; q2 = n2; q3 = n3; up = nup;
    chb[j * 32 + ln] = (unsigned char)bits;
}

__global__ __launch_bounds__(128) void mas_kernel(const int* __restrict__ tokl,
                                                  const int* __restrict__ featl,
                                                  float* __restrict__ out) {
    __shared__ unsigned char ch[TN * 32];   // [j][ln] nibble of rows 4ln..4ln+3
    __shared__ int dsh[SN];
    int b = blockIdx.x;
    int tid = threadIdx.x;
    float* hard = out + BN * SN + (size_t)BN * SN * TN + ((size_t)b * SN) * TN;
    float* dout = out + (size_t)b * SN;
    dsh[tid] = 0;
    __syncthreads();
    if (tid < 32) {
        int ln = tid;
        const float4* src = reinterpret_cast<const float4*>(g_lpT + (size_t)b * TN * SN) + ln;
        float4 A[8], Bq[8];
#pragma unroll
        for (int q = 0; q < 8; ++q) A[q] = src[(size_t)q * 32];
#pragma unroll
        for (int q = 0; q < 8; ++q) Bq[q] = src[(size_t)(8 + q) * 32];
        // peel group 0 (j = 0..7); at j=0 all q are NEGV so up = NEGV exactly
        float q0 = (ln == 0) ? A[0].x : NEGV;
        float q1 = NEGV, q2 = NEGV, q3 = NEGV, up = NEGV;
        ch[ln] = 0;
#pragma unroll
        for (int jj = 1; jj < 8; ++jj)
            dpn(A[jj], jj, ln, q0, q1, q2, q3, up, ch);
        // steady state: branch-free, 2-group software pipeline
#pragma unroll 1
        for (int c = 1; c < 63; c += 2) {
#pragma unroll
            for (int q = 0; q < 8; ++q) A[q] = src[(size_t)((c + 1) * 8 + q) * 32];
#pragma unroll
            for (int jj = 0; jj < 8; ++jj)
                dpn(Bq[jj], c * 8 + jj, ln, q0, q1, q2, q3, up, ch);
#pragma unroll
            for (int q = 0; q < 8; ++q) Bq[q] = src[(size_t)((c + 2) * 8 + q) * 32];
#pragma unroll
            for (int jj = 0; jj < 8; ++jj)
                dpn(A[jj], (c + 1) * 8 + jj, ln, q0, q1, q2, q3, up, ch);
        }
#pragma unroll
        for (int jj = 0; jj < 8; ++jj)
            dpn(Bq[jj], 63 * 8 + jj, ln, q0, q1, q2, q3, up, ch);
        __syncwarp();
        if (tid == 0) {
            int i = tokl[b] - 1;
            int fl = featl[b];
            int j = fl - 1;
            int bit = (j > 0) ? (int)((ch[j * 32 + (i >> 2)] >> (i & 3)) & 1u) : 0;
            unsigned B0 = 0, B1 = 0;
            if (j >= 1) {
                int i1 = (i > 0) ? i - 1 : 0;
                B0 = ch[(j - 1) * 32 + (i >> 2)];
                B1 = ch[(j - 1) * 32 + (i1 >> 2)];
            }
            int run = 0, previ = i;
            while (j > 0) {
                hard[(size_t)i * TN + j] = 1.0f;
                ++run;
                int inext = i - bit;
                unsigned bsel = bit ? B1 : B0;
                int nbit = (int)((bsel >> (inext & 3)) & 1u);
                if (j >= 2) {
                    int i1 = (inext > 0) ? inext - 1 : 0;
                    B0 = ch[(j - 2) * 32 + (inext >> 2)];
                    B1 = ch[(j - 2) * 32 + (i1 >> 2)];
                }
                if (inext != i) { dsh[previ] = run; run = 0; previ = inext; }
                i = inext; bit = nbit;
                --j;
            }
            hard[(size_t)i * TN] = 1.0f;
            ++run;
            dsh[previ] = run;
        }
    }
    __syncthreads();
    dout[tid] = (float)dsh[tid];
}

extern "C" void kernel_launch(void* const* d_in, const int* in_sizes, int n_in,
                              void* d_out, int out_size) {
    const float* h  = (const float*)d_in[0];
    const float* m  = (const float*)d_in[1];
    const int* tokl = (const int*)d_in[2];
    const int* fetl = (const int*)d_in[3];
    const float* W1 = (const float*)d_in[5];
    const float* b1 = (const float*)d_in[6];
    const float* W2 = (const float*)d_in[7];
    const float* b2 = (const float*)d_in[8];
    const float* F1 = (const float*)d_in[9];
    const float* g1 = (const float*)d_in[10];
    const float* F2 = (const float*)d_in[11];
    const float* g2 = (const float*)d_in[12];
    const float* F3 = (const float*)d_in[13];
    const float* g3 = (const float*)d_in[14];
    float* out = (float*)d_out;

    transpose_kernel<<<576, 256>>>(W1, W2, F1, F2, F3);
    conv_all_kernel<<<320, 256>>>(h, m, b1, b2, g1, g2, g3);
    dist_softmax_kernel<<<dim3(BN, TN / 16), 128>>>(tokl, out);
    mas_kernel<<<BN, 128>>>(tokl, fetl, out);
}

// round 9
// speedup vs baseline: 1.3461x; 1.0075x over previous
#include <cuda_runtime.h>
#include <math.h>

#define BN 8
#define SN 128
#define TN 512
#define DT 256
#define DF 80
#define NEGV (-1e9f)

typedef unsigned long long ull;

__device__ float g_ht[BN * SN * DT];
__device__ float g_mt[BN * TN * DT];
__device__ float g_lpT[BN * TN * SN];   // transposed log_a_soft [b][t][s]
__device__ float W1t[768 * DT];
__device__ float W2t[DT * DT];
__device__ float F1t[240 * DT];
__device__ float F2t[768 * DT];
__device__ float F3t[DT * DT];

__device__ __forceinline__ ull pk2(float lo, float hi) {
    ull r; asm("mov.b64 %0,{%1,%2};" : "=l"(r) : "f"(lo), "f"(hi)); return r;
}
__device__ __forceinline__ void upk2(ull v, float& lo, float& hi) {
    asm("mov.b64 {%0,%1},%2;" : "=f"(lo), "=f"(hi) : "l"(v));
}
__device__ __forceinline__ ull fma2(ull a, ull b, ull c) {
    ull d; asm("fma.rn.f32x2 %0,%1,%2,%3;" : "=l"(d) : "l"(a), "l"(b), "l"(c)); return d;
}
__device__ __forceinline__ ull add2(ull a, ull b) {
    ull d; asm("add.rn.f32x2 %0,%1,%2;" : "=l"(d) : "l"(a), "l"(b)); return d;
}
__device__ __forceinline__ ull ld64s(const float* p) { return *reinterpret_cast<const ull*>(p); }

// --------------------------------------------------------------------------
// Coalesced weight transposes.
// --------------------------------------------------------------------------
__global__ __launch_bounds__(256) void transpose_kernel(const float* __restrict__ W1,
                                                        const float* __restrict__ W2,
                                                        const float* __restrict__ F1,
                                                        const float* __restrict__ F2,
                                                        const float* __restrict__ F3) {
    __shared__ float tile[32][33];
    int blk = blockIdx.x;
    const float* src; float* dst; int C; int t;
    if (blk < 192)      { src = W1; dst = W1t; C = 768; t = blk; }
    else if (blk < 256) { src = W2; dst = W2t; C = 256; t = blk - 192; }
    else if (blk < 320) { src = F1; dst = F1t; C = 240; t = blk - 256; }
    else if (blk < 512) { src = F2; dst = F2t; C = 768; t = blk - 320; }
    else                { src = F3; dst = F3t; C = 256; t = blk - 512; }
    int Ct = (C + 31) >> 5;
    int tr = t / Ct, tc = t - tr * Ct;
    int tx = threadIdx.x & 31, ty = threadIdx.x >> 5;
#pragma unroll
    for (int i = 0; i < 4; ++i) {
        int r = tr * 32 + ty + i * 8, cc = tc * 32 + tx;
        tile[ty + i * 8][tx] = (cc < C) ? src[(size_t)r * C + cc] : 0.f;
    }
    __syncthreads();
#pragma unroll
    for (int i = 0; i < 4; ++i) {
        int cc = tc * 32 + ty + i * 8, r = tr * 32 + tx;
        if (cc < C) dst[(size_t)cc * 256 + r] = tile[tx][ty + i * 8];
    }
}

// --------------------------------------------------------------------------
// Packed conv helpers.
// --------------------------------------------------------------------------
template <int NC, int RS, int NP>
__device__ __forceinline__ void conv3pairs(const float* src, const float* wt, float bias, ull* acc) {
    ull bb = pk2(bias, bias);
#pragma unroll
    for (int i = 0; i < NP; ++i) acc[i] = bb;
    for (int ci = 0; ci < NC; ++ci) {
        const float* x = src + ci * RS;
        ull P[NP + 1];
#pragma unroll
        for (int i = 0; i <= NP; ++i) P[i] = ld64s(x + 2 * i);
        float lo[NP + 1], hi[NP + 1];
#pragma unroll
        for (int i = 0; i <= NP; ++i) upk2(P[i], lo[i], hi[i]);
        ull O[NP];
#pragma unroll
        for (int i = 0; i < NP; ++i) O[i] = pk2(hi[i], lo[i + 1]);
        const float* wp = wt + ci * 3 * DT;
        ull w0 = pk2(wp[0], wp[0]), w1 = pk2(wp[DT], wp[DT]), w2 = pk2(wp[2 * DT], wp[2 * DT]);
#pragma unroll
        for (int i = 0; i < NP; ++i) acc[i] = fma2(w0, P[i], acc[i]);
#pragma unroll
        for (int i = 0; i < NP; ++i) acc[i] = fma2(w1, O[i], acc[i]);
#pragma unroll
        for (int i = 0; i < NP; ++i) acc[i] = fma2(w2, P[i + 1], acc[i]);
    }
}

// RS must be a multiple of 4 and rows 16B-aligned (true for B0/yT, RS=16).
template <int NP>
__device__ __forceinline__ void conv1pairs(const float* src, int RS, const float* wt, float bias, ull* acc) {
    ull bb = pk2(bias, bias);
#pragma unroll
    for (int i = 0; i < NP; ++i) acc[i] = bb;
    for (int ci = 0; ci < DT; ++ci) {
        const float4* x4 = reinterpret_cast<const float4*>(src + ci * RS);
        float w = wt[ci * DT];
        ull wpk = pk2(w, w);
#pragma unroll
        for (int i = 0; i < NP / 2; ++i) {
            float4 v = x4[i];
            acc[2 * i]     = fma2(wpk, pk2(v.x, v.y), acc[2 * i]);
            acc[2 * i + 1] = fma2(wpk, pk2(v.z, v.w), acc[2 * i + 1]);
        }
    }
}

// --------------------------------------------------------------------------
// Fused conv: blocks [0,256) feat path, [256,320) text path.  256 thr = chan.
// --------------------------------------------------------------------------
__global__ __launch_bounds__(256) void conv_all_kernel(const float* __restrict__ h,
                                                       const float* __restrict__ m,
                                                       const float* __restrict__ b1v,
                                                       const float* __restrict__ b2v,
                                                       const float* __restrict__ g1v,
                                                       const float* __restrict__ g2v,
                                                       const float* __restrict__ g3v) {
    __shared__ __align__(16) float sbuf[10304];
    int tid = threadIdx.x, blk = blockIdx.x, c = tid;
    if (blk < 256) {
        float* mT = sbuf;            // [80][20]
        float* A0 = sbuf + 1600;     // [256][18]
        float* B0 = sbuf + 6208;     // [256][16]
        int b = blk >> 5, t0 = (blk & 31) << 4;
        for (int idx = tid; idx < 1600; idx += 256) {
            int p = idx / 80, ci = idx - p * 80;
            int t = t0 - 2 + p;
            mT[ci * 20 + p] = (t >= 0 && t < TN) ? m[((size_t)(b * TN + t)) * DF + ci] : 0.f;
        }
        __syncthreads();
        {
            ull acc[9];
            conv3pairs<DF, 20, 9>(mT, F1t + c, g1v[c], acc);
#pragma unroll
            for (int i = 0; i < 9; ++i) {
                float v0, v1; upk2(acc[i], v0, v1);
                int g = t0 - 1 + 2 * i;
                A0[c * 18 + 2 * i] = (g >= 0 && g < TN) ? fmaxf(v0, 0.f) : 0.f;
                ++g;
                A0[c * 18 + 2 * i + 1] = (g >= 0 && g < TN) ? fmaxf(v1, 0.f) : 0.f;
            }
        }
        __syncthreads();
        {
            ull acc[8];
            conv3pairs<DT, 18, 8>(A0, F2t + c, g2v[c], acc);
#pragma unroll
            for (int i = 0; i < 8; ++i) {
                float v0, v1; upk2(acc[i], v0, v1);
                B0[c * 16 + 2 * i] = fmaxf(v0, 0.f);
                B0[c * 16 + 2 * i + 1] = fmaxf(v1, 0.f);
            }
        }
        __syncthreads();
        {
            ull acc[8];
            conv1pairs<8>(B0, 16, F3t + c, g3v[c], acc);
#pragma unroll
            for (int i = 0; i < 8; ++i) {
                float v0, v1; upk2(acc[i], v0, v1);
                g_mt[((size_t)(b * TN + t0 + 2 * i)) * DT + c] = v0;
                g_mt[((size_t)(b * TN + t0 + 2 * i + 1)) * DT + c] = v1;
            }
        }
    } else {
        float* hT = sbuf;            // [256][18]
        float* yT = sbuf + 4608;     // [256][16]
        int q = blk - 256;
        int b = q >> 3, s0 = (q & 7) << 4;
        for (int idx = tid; idx < 4608; idx += 256) {
            int p = idx >> 8, cc = idx & 255;
            int s = s0 - 1 + p;
            hT[cc * 18 + p] = (s >= 0 && s < SN) ? h[((size_t)(b * SN + s)) * DT + cc] : 0.f;
        }
        __syncthreads();
        {
            ull acc[8];
            conv3pairs<DT, 18, 8>(hT, W1t + c, b1v[c], acc);
#pragma unroll
            for (int i = 0; i < 8; ++i) {
                float v0, v1; upk2(acc[i], v0, v1);
                yT[c * 16 + 2 * i] = fmaxf(v0, 0.f);
                yT[c * 16 + 2 * i + 1] = fmaxf(v1, 0.f);
            }
        }
        __syncthreads();
        {
            ull acc[8];
            conv1pairs<8>(yT, 16, W2t + c, b2v[c], acc);
#pragma unroll
            for (int i = 0; i < 8; ++i) {
                float v0, v1; upk2(acc[i], v0, v1);
                g_ht[((size_t)(b * SN + s0 + 2 * i)) * DT + c] = v0;
                g_ht[((size_t)(b * SN + s0 + 2 * i + 1)) * DT + c] = v1;
            }
        }
    }
}

// --------------------------------------------------------------------------
// L2 distance + log_softmax + transposed side-output g_lpT.
// --------------------------------------------------------------------------
__global__ __launch_bounds__(128) void dist_softmax_kernel(const int* __restrict__ tokl,
                                                           float* __restrict__ out) {
    __shared__ float A[SN][33];
    __shared__ __align__(8) float Bs[32][18];
    __shared__ float Z[SN][17];
    __shared__ float mls[16];
    int b = blockIdx.x, t0 = blockIdx.y * 16;
    int tid = threadIdx.x;
    int ts = tid >> 2, tt = tid & 3;
    ull acc[4][2];
#pragma unroll
    for (int r = 0; r < 4; ++r) { acc[r][0] = 0ULL; acc[r][1] = 0ULL; }
    for (int cch = 0; cch < 8; ++cch) {
        int k0 = cch * 32;
        for (int idx = tid; idx < SN * 32; idx += 128) {
            int s = idx >> 5, kk = idx & 31;
            A[s][kk] = g_ht[((size_t)(b * SN + s)) * DT + k0 + kk];
        }
        for (int idx = tid; idx < 16 * 32; idx += 128) {
            int t = idx >> 5, kk = idx & 31;
            Bs[kk][t] = -g_mt[((size_t)(b * TN + t0 + t)) * DT + k0 + kk];
        }
        __syncthreads();
#pragma unroll 4
        for (int kk = 0; kk < 32; ++kk) {
            ull bq0 = ld64s(&Bs[kk][tt * 4]);
            ull bq1 = ld64s(&Bs[kk][tt * 4 + 2]);
#pragma unroll
            for (int r = 0; r < 4; ++r) {
                float av = A[ts * 4 + r][kk];
                ull ap = pk2(av, av);
                ull d0 = add2(ap, bq0);
                acc[r][0] = fma2(d0, d0, acc[r][0]);
                ull d1 = add2(ap, bq1);
                acc[r][1] = fma2(d1, d1, acc[r][1]);
            }
        }
        __syncthreads();
    }
    int tok = tokl[b];
#pragma unroll
    for (int r = 0; r < 4; ++r) {
        int s = ts * 4 + r;
        float v[4];
        upk2(acc[r][0], v[0], v[1]);
        upk2(acc[r][1], v[2], v[3]);
#pragma unroll
        for (int j = 0; j < 4; ++j) {
            float dd = (s < tok) ? sqrtf(fmaxf(v[j], 0.f)) : 0.f;
            Z[s][tt * 4 + j] = -dd;
        }
    }
    __syncthreads();
    int tcol = tid >> 3, l = tid & 7;
    float mx = -3.4e38f;
#pragma unroll
    for (int i2 = 0; i2 < 16; ++i2) mx = fmaxf(mx, Z[l * 16 + i2][tcol]);
    mx = fmaxf(mx, __shfl_xor_sync(0xffffffffu, mx, 4));
    mx = fmaxf(mx, __shfl_xor_sync(0xffffffffu, mx, 2));
    mx = fmaxf(mx, __shfl_xor_sync(0xffffffffu, mx, 1));
    float sm = 0.f;
#pragma unroll
    for (int i2 = 0; i2 < 16; ++i2) sm += expf(Z[l * 16 + i2][tcol] - mx);
    sm += __shfl_xor_sync(0xffffffffu, sm, 4);
    sm += __shfl_xor_sync(0xffffffffu, sm, 2);
    sm += __shfl_xor_sync(0xffffffffu, sm, 1);
    if (l == 0) mls[tcol] = mx + logf(sm);
    __syncthreads();
    float* out_log = out + BN * SN;
    float* out_hard = out + BN * SN + (size_t)BN * SN * TN;
    for (int idx = tid; idx < SN * 16; idx += 128) {
        int s = idx >> 4, tl = idx & 15;
        size_t o = ((size_t)(b * SN + s)) * TN + t0 + tl;
        out_log[o] = Z[s][tl] - mls[tl];
        out_hard[o] = 0.f;
    }
    for (int idx = tid; idx < 16 * SN; idx += 128) {
        int tl = idx >> 7, s = idx & 127;
        g_lpT[((size_t)(b * TN) + t0 + tl) * SN + s] = Z[s][tl] - mls[tl];
    }
}

// --------------------------------------------------------------------------
// MAS v6: 4-deep register pipeline (prefetch ~24 steps / ~800+cyc ahead),
// branch-free scalar DP (identical math to v5), nibble STS.U8 choice bits,
// dual-prefetch backtrack.
// --------------------------------------------------------------------------
__device__ __forceinline__ void dpn(float4 Lq, int j, int ln,
                                    float& q0, float& q1, float& q2, float& q3,
                                    float& up, unsigned char* chb) {
    float s0 = (ln == 0) ? NEGV : up;
    unsigned bits = (unsigned)(s0 >= q0)
                  | ((unsigned)(q0 >= q1) << 1)
                  | ((unsigned)(q1 >= q2) << 2)
                  | ((unsigned)(q2 >= q3) << 3);
    float n3 = Lq.w + fmaxf(q3, q2);
    float nup = __shfl_up_sync(0xffffffffu, n3, 1);
    float n0 = Lq.x + fmaxf(q0, s0);
    float n1 = Lq.y + fmaxf(q1, q0);
    float n2 = Lq.z + fmaxf(q2, q1);
    q0 = n0; q1 = n1; q2 = n2; q3 = n3; up = nup;
    chb[j * 32 + ln] = (unsigned char)bits;
}

__global__ __launch_bounds__(128) void mas_kernel(const int* __restrict__ tokl,
                                                  const int* __restrict__ featl,
                                                  float* __restrict__ out) {
    __shared__ unsigned char ch[TN * 32];   // [j][ln] nibble of rows 4ln..4ln+3
    __shared__ int dsh[SN];
    int b = blockIdx.x;
    int tid = threadIdx.x;
    float* hard = out + BN * SN + (size_t)BN * SN * TN + ((size_t)b * SN) * TN;
    float* dout = out + (size_t)b * SN;
    dsh[tid] = 0;
    __syncthreads();
    if (tid < 32) {
        int ln = tid;
        const float4* src = reinterpret_cast<const float4*>(g_lpT + (size_t)b * TN * SN) + ln;
        float4 S0[8], S1[8], S2[8], S3[8];
#define PF(BUF, GRP) { int _g = (GRP) < 64 ? (GRP) : 63; \
    _Pragma("unroll") for (int q = 0; q < 8; ++q) BUF[q] = src[(size_t)(_g * 8 + q) * 32]; }
#define PROC(BUF, GRP) { _Pragma("unroll") for (int jj = 0; jj < 8; ++jj) \
    dpn(BUF[jj], (GRP) * 8 + jj, ln, q0, q1, q2, q3, up, ch); }
        PF(S0, 0); PF(S1, 1); PF(S2, 2); PF(S3, 3);
        // peel group 0 (j = 0..7); at j=0 all q are NEGV so up = NEGV exactly
        float q0 = (ln == 0) ? S0[0].x : NEGV;
        float q1 = NEGV, q2 = NEGV, q3 = NEGV, up = NEGV;
        ch[ln] = 0;
#pragma unroll
        for (int jj = 1; jj < 8; ++jj)
            dpn(S0[jj], jj, ln, q0, q1, q2, q3, up, ch);
        PF(S0, 4);
        // steady state: groups 1..60, 4-slot rotation, prefetch 3 groups deep
#pragma unroll 1
        for (int it = 0; it < 15; ++it) {
            int base = 1 + it * 4;
            PROC(S1, base);     PF(S1, base + 4);
            PROC(S2, base + 1); PF(S2, base + 5);
            PROC(S3, base + 2); PF(S3, base + 6);
            PROC(S0, base + 3); PF(S0, base + 7);
        }
        PROC(S1, 61); PROC(S2, 62); PROC(S3, 63);
#undef PF
#undef PROC
        __syncwarp();
        if (tid == 0) {
            int i = tokl[b] - 1;
            int fl = featl[b];
            int j = fl - 1;
            int bit = (j > 0) ? (int)((ch[j * 32 + (i >> 2)] >> (i & 3)) & 1u) : 0;
            unsigned B0 = 0, B1 = 0;
            if (j >= 1) {
                int i1 = (i > 0) ? i - 1 : 0;
                B0 = ch[(j - 1) * 32 + (i >> 2)];
                B1 = ch[(j - 1) * 32 + (i1 >> 2)];
            }
            int run = 0, previ = i;
            while (j > 0) {
                hard[(size_t)i * TN + j] = 1.0f;
                ++run;
                int inext = i - bit;
                unsigned bsel = bit ? B1 : B0;
                int nbit = (int)((bsel >> (inext & 3)) & 1u);
                if (j >= 2) {
                    int i1 = (inext > 0) ? inext - 1 : 0;
                    B0 = ch[(j - 2) * 32 + (inext >> 2)];
                    B1 = ch[(j - 2) * 32 + (i1 >> 2)];
                }
                if (inext != i) { dsh[previ] = run; run = 0; previ = inext; }
                i = inext; bit = nbit;
                --j;
            }
            hard[(size_t)i * TN] = 1.0f;
            ++run;
            dsh[previ] = run;
        }
    }
    __syncthreads();
    dout[tid] = (float)dsh[tid];
}

extern "C" void kernel_launch(void* const* d_in, const int* in_sizes, int n_in,
                              void* d_out, int out_size) {
    const float* h  = (const float*)d_in[0];
    const float* m  = (const float*)d_in[1];
    const int* tokl = (const int*)d_in[2];
    const int* fetl = (const int*)d_in[3];
    const float* W1 = (const float*)d_in[5];
    const float* b1 = (const float*)d_in[6];
    const float* W2 = (const float*)d_in[7];
    const float* b2 = (const float*)d_in[8];
    const float* F1 = (const float*)d_in[9];
    const float* g1 = (const float*)d_in[10];
    const float* F2 = (const float*)d_in[11];
    const float* g2 = (const float*)d_in[12];
    const float* F3 = (const float*)d_in[13];
    const float* g3 = (const float*)d_in[14];
    float* out = (float*)d_out;

    transpose_kernel<<<576, 256>>>(W1, W2, F1, F2, F3);
    conv_all_kernel<<<320, 256>>>(h, m, b1, b2, g1, g2, g3);
    dist_softmax_kernel<<<dim3(BN, TN / 16), 128>>>(tokl, out);
    mas_kernel<<<BN, 128>>>(tokl, fetl, out);
}